// round 16
// baseline (speedup 1.0000x reference)
#include <cuda_runtime.h>
#include <cuda_fp16.h>
#include <cstdint>
#include <math.h>

#define N_TOK 8192
#define C_DIM 128
#define D_DIM 64

#define BM 64
#define BN 64
#define NTILES (N_TOK / BN)

// ===========================================================================
// Globals (allocation-free scratch), all fp16
// ===========================================================================
__device__ __half g_q [N_TOK * D_DIM];   // [n][d], pre-scaled by log2e/8
__device__ __half g_k [N_TOK * D_DIM];   // [n][d]
__device__ __half g_vT[D_DIM * N_TOK];   // [d][n]

// ===========================================================================
// PTX helpers (base-ISA only)
// ===========================================================================
__device__ __forceinline__ uint32_t smem_u32(const void* p) {
    uint32_t a;
    asm("{ .reg .u64 t; cvta.to.shared.u64 t, %1; cvt.u32.u64 %0, t; }"
        : "=r"(a) : "l"(p));
    return a;
}
#define CP16(dst, src) \
    asm volatile("cp.async.cg.shared.global [%0], [%1], 16;" \
        :: "r"(dst), "l"(src))
#define CP_COMMIT() asm volatile("cp.async.commit_group;")
#define CP_WAIT1()  asm volatile("cp.async.wait_group 1;" ::: "memory")
#define BAR_GRP(id) \
    asm volatile("bar.sync %0, 64;" :: "r"(id) : "memory")

#define LDSM4(r, addr) \
    asm volatile("ldmatrix.sync.aligned.m8n8.x4.shared.b16 {%0,%1,%2,%3}, [%4];" \
        : "=r"((r)[0]), "=r"((r)[1]), "=r"((r)[2]), "=r"((r)[3]) : "r"(addr))

__device__ __forceinline__ void mma16816(float d[4], const uint32_t a[4],
                                         const uint32_t b[2]) {
    asm volatile(
        "mma.sync.aligned.m16n8k16.row.col.f32.f16.f16.f32 "
        "{%0,%1,%2,%3}, {%4,%5,%6,%7}, {%8,%9}, {%0,%1,%2,%3};"
        : "+f"(d[0]), "+f"(d[1]), "+f"(d[2]), "+f"(d[3])
        : "r"(a[0]), "r"(a[1]), "r"(a[2]), "r"(a[3]), "r"(b[0]), "r"(b[1]));
}

// fp16-accumulator variant: D/C are 2 regs of fp16x2 (rows r, r+8)
__device__ __forceinline__ void mma16816h(uint32_t d[2], const uint32_t a[4],
                                          const uint32_t b[2]) {
    asm volatile(
        "mma.sync.aligned.m16n8k16.row.col.f16.f16.f16.f16 "
        "{%0,%1}, {%2,%3,%4,%5}, {%6,%7}, {%0,%1};"
        : "+r"(d[0]), "+r"(d[1])
        : "r"(a[0]), "r"(a[1]), "r"(a[2]), "r"(a[3]), "r"(b[0]), "r"(b[1]));
}

// packs: result.lo = f16(a), result.hi = f16(b)
#define CVT_F16X2(result, a, b) \
    asm("cvt.rn.f16x2.f32 %0, %1, %2;" : "=r"(result) : "f"(b), "f"(a))
// packed fp16x2 exp2 (scores pre-scaled by log2e)
#define HEX2(r, x) asm("ex2.approx.f16x2 %0, %1;" : "=r"(r) : "r"(x))

// ===========================================================================
// Kernel 1: tensor-core QKV (W converted in-kernel), unchanged from R15.
// ===========================================================================
#define QT_XLO 0
#define QT_XHI 8192
#define QT_W   16384
#define QT_VS  65536
#define QT_SMEM (QT_VS + 64 * 72 * 2)     // 74752 bytes

__global__ __launch_bounds__(256) void qkv_tc(
    const float* __restrict__ hid,
    const float* __restrict__ wq,
    const float* __restrict__ wk,
    const float* __restrict__ wv)
{
    extern __shared__ char sm[];
    const uint32_t sb = smem_u32(sm);
    const int tid  = threadIdx.x;
    const int lane = tid & 31;
    const int w    = tid >> 5;
    const int n0   = blockIdx.x * 64;
    const int bt   = n0 >> 8;
    const int hw0  = n0 & 255;
    const float* base = hid + (size_t)bt * (C_DIM * 256) + hw0;

    #pragma unroll
    for (int m = 0; m < 3; m++) {
        const float* wm = (m == 0) ? wq : (m == 1) ? wk : wv;
        const float sc = (m == 0) ? 0.1803368801f : 1.0f;   // /8 * log2e
        #pragma unroll
        for (int i = 0; i < 16; i++) {
            int id = tid + i * 256;
            int o  = id & 63;
            int c2 = id >> 6;
            float f0 = __ldg(wm + (2 * c2)     * 64 + o) * sc;
            float f1 = __ldg(wm + (2 * c2 + 1) * 64 + o) * sc;
            uint32_t h;
            CVT_F16X2(h, f0, f1);
            uint32_t tile = QT_W + (uint32_t)(m * 2 + (c2 >> 5)) * 8192;
            uint32_t off = (uint32_t)o * 128
                         + (uint32_t)(((c2 & 31) * 4) ^ ((o & 7) << 4));
            *(uint32_t*)(sm + tile + off) = h;
        }
    }

    #pragma unroll
    for (int i = 0; i < 16; i++) {
        int idx = tid + i * 256;
        int r = idx & 63, c2 = idx >> 6;
        float f0 = base[(2 * c2)     * 256 + r];
        float f1 = base[(2 * c2 + 1) * 256 + r];
        __half2 h = __floats2half2_rn(f0, f1);
        uint32_t tile = (c2 < 32) ? QT_XLO : QT_XHI;
        uint32_t boff = (uint32_t)r * 128
                      + (uint32_t)(((c2 & 31) * 4) ^ ((r & 7) << 4));
        *(__half2*)(sm + tile + boff) = h;
    }
    __syncthreads();

    const int r0 = (w & 3) * 16;
    uint32_t af[8][4];
    {
        uint32_t cxor = (uint32_t)(lane & 7) << 4;
        uint32_t rowb = sb + (uint32_t)(r0 + (lane & 15)) * 128;
        #pragma unroll
        for (int ks = 0; ks < 8; ks++) {
            uint32_t tile = (ks < 4) ? QT_XLO : QT_XHI;
            uint32_t ch = (uint32_t)((ks & 3) * 32 + ((lane >> 4) << 4));
            LDSM4(af[ks], rowb + tile + (ch ^ cxor));
        }
    }

    const uint32_t browB = (uint32_t)(lane & 7) * 128;
    const uint32_t cA = (uint32_t)((((lane >> 3) & 3) << 4) ^ ((lane & 7) << 4));
    const uint32_t cB = cA ^ 64u;

    float oq[8][4];
    #pragma unroll
    for (int nb = 0; nb < 8; nb++)
        #pragma unroll
        for (int j = 0; j < 4; j++) oq[nb][j] = 0.f;
    {
        uint32_t wbase = sb + QT_W + ((w < 4) ? 0 : 16384);
        #pragma unroll
        for (int nb = 0; nb < 8; nb++) {
            uint32_t rl = wbase + (uint32_t)nb * 1024 + browB;
            uint32_t rh = rl + 8192;
            uint32_t b01[4], b23[4], b45[4], b67[4];
            LDSM4(b01, rl + cA); LDSM4(b23, rl + cB);
            LDSM4(b45, rh + cA); LDSM4(b67, rh + cB);
            mma16816(oq[nb], af[0], b01 + 0); mma16816(oq[nb], af[1], b01 + 2);
            mma16816(oq[nb], af[2], b23 + 0); mma16816(oq[nb], af[3], b23 + 2);
            mma16816(oq[nb], af[4], b45 + 0); mma16816(oq[nb], af[5], b45 + 2);
            mma16816(oq[nb], af[6], b67 + 0); mma16816(oq[nb], af[7], b67 + 2);
        }
    }
    float ov[4][4];
    #pragma unroll
    for (int j = 0; j < 4; j++)
        #pragma unroll
        for (int c = 0; c < 4; c++) ov[j][c] = 0.f;
    const int nb0 = (w < 4) ? 0 : 4;
    {
        uint32_t vbase = sb + QT_W + 32768;
        #pragma unroll
        for (int j = 0; j < 4; j++) {
            uint32_t rl = vbase + (uint32_t)(nb0 + j) * 1024 + browB;
            uint32_t rh = rl + 8192;
            uint32_t b01[4], b23[4], b45[4], b67[4];
            LDSM4(b01, rl + cA); LDSM4(b23, rl + cB);
            LDSM4(b45, rh + cA); LDSM4(b67, rh + cB);
            mma16816(ov[j], af[0], b01 + 0); mma16816(ov[j], af[1], b01 + 2);
            mma16816(ov[j], af[2], b23 + 0); mma16816(ov[j], af[3], b23 + 2);
            mma16816(ov[j], af[4], b45 + 0); mma16816(ov[j], af[5], b45 + 2);
            mma16816(ov[j], af[6], b67 + 0); mma16816(ov[j], af[7], b67 + 2);
        }
    }

    {
        __half* dst = (w < 4) ? g_q : g_k;
        const int row = r0 + (lane >> 2);
        const int c0  = (lane & 3) * 2;
        #pragma unroll
        for (int nb = 0; nb < 8; nb++) {
            *(__half2*)(dst + (size_t)(n0 + row) * 64 + nb * 8 + c0)
                = __floats2half2_rn(oq[nb][0], oq[nb][1]);
            *(__half2*)(dst + (size_t)(n0 + row + 8) * 64 + nb * 8 + c0)
                = __floats2half2_rn(oq[nb][2], oq[nb][3]);
        }
    }
    {
        __half* vsh = (__half*)(sm + QT_VS);
        const int row = r0 + (lane >> 2);
        const int c0  = (lane & 3) * 2;
        #pragma unroll
        for (int j = 0; j < 4; j++) {
            int col = (nb0 + j) * 8 + c0;
            vsh[(col    ) * 72 + row    ] = __float2half(ov[j][0]);
            vsh[(col + 1) * 72 + row    ] = __float2half(ov[j][1]);
            vsh[(col    ) * 72 + row + 8] = __float2half(ov[j][2]);
            vsh[(col + 1) * 72 + row + 8] = __float2half(ov[j][3]);
        }
    }
    __syncthreads();
    {
        __half* vsh = (__half*)(sm + QT_VS);
        #pragma unroll
        for (int i = 0; i < 2; i++) {
            int id = tid + i * 256;
            int d = id >> 3, ch = id & 7;
            uint4 u = *(uint4*)&vsh[d * 72 + ch * 8];
            *(uint4*)((char*)g_vT + (size_t)d * 16384 + n0 * 2 + ch * 16) = u;
        }
    }
}

// ===========================================================================
// Kernel 2: flash attention; S-GEMM in fp16 accumulators (D = A-frag of PV),
// softmax = 2x HEX2 per block, zero CVTs. PV/rowsum remain fp32-accum.
// 128 CTAs x 256 threads; FOUR decoupled 64-thread groups (2 warps each).
// ===========================================================================
#define SM_Q   0
#define SM_KV  8192
#define KVBUF  16384            // k 0 | v 8192
#define SMEM_TOTAL (SM_KV + 8 * KVBUF)    // 139264 bytes

__device__ __forceinline__ void prefetch_tile(uint32_t kvbuf, int t, int lt)
{
    #pragma unroll
    for (int i = 0; i < 8; i++) {
        int id = lt + i * 64;
        int row = id >> 3;
        int ch  = (id & 7) * 16;
        uint32_t sw = (uint32_t)row * 128 + (uint32_t)(ch ^ ((row & 7) << 4));
        CP16(kvbuf +         sw, (const char*)g_k  + t * 8192 + row * 128 + ch);
        CP16(kvbuf + 8192 + sw, (const char*)g_vT + (size_t)row * 16384 + t * 128 + ch);
    }
}

// exp2 of the fp16 S fragment -> phi (A-fragment of PV) directly
#define SOFTMAX_ONE(SH, PHI, nt) do {                                         \
    const int kk = (nt) >> 1, u = ((nt) & 1) * 2;                             \
    HEX2(PHI[kk][u],     SH[nt][0]);                                          \
    HEX2(PHI[kk][u + 1], SH[nt][1]);                                          \
} while (0)

// S (fp16 accum) for nt = base..base+3, both m-fragments reuse B-fragments
#define S_HALF(base) do {                                                     \
    uint32_t B[4][8];                                                         \
    _Pragma("unroll")                                                         \
    for (int j = 0; j < 4; j++) {                                             \
        uint32_t rb = kv + (uint32_t)((base) + j) * 1024 + browB;             \
        LDSM4(&B[j][0], rb + cA);                                             \
        LDSM4(&B[j][4], rb + cB);                                             \
    }                                                                         \
    _Pragma("unroll")                                                         \
    for (int ks = 0; ks < 4; ks++)                                            \
        _Pragma("unroll")                                                     \
        for (int j = 0; j < 4; j++) {                                         \
            mma16816h(sh0[(base) + j], qf[0][ks], &B[j][ks * 2]);             \
            mma16816h(sh1[(base) + j], qf[1][ks], &B[j][ks * 2]);             \
        }                                                                     \
} while (0)

// PV quarter (fp32 accum): both m-fragments reuse each V B-fragment
#define PV_QTR(base, COFF, PA, PB) do {                                       \
    uint32_t B[4][4];                                                         \
    _Pragma("unroll")                                                         \
    for (int j = 0; j < 4; j++) {                                             \
        uint32_t rb = kv + 8192 + (uint32_t)((base) + j) * 1024 + browB;      \
        LDSM4(&B[j][0], rb + (COFF));                                         \
    }                                                                         \
    _Pragma("unroll")                                                         \
    for (int j = 0; j < 4; j++) {                                             \
        mma16816(o0[(base) + j], phi0[PA], &B[j][0]);                         \
        mma16816(o1[(base) + j], phi1[PA], &B[j][0]);                         \
    }                                                                         \
    _Pragma("unroll")                                                         \
    for (int j = 0; j < 4; j++) {                                             \
        mma16816(o0[(base) + j], phi0[PB], &B[j][2]);                         \
        mma16816(o1[(base) + j], phi1[PB], &B[j][2]);                         \
    }                                                                         \
} while (0)

__global__ __launch_bounds__(256, 1) void attn_mma(float* __restrict__ out)
{
    extern __shared__ char sm[];
    const uint32_t sb = smem_u32(sm);
    const int tid  = threadIdx.x;
    const int lane = tid & 31;
    const int wid  = tid >> 5;        // 0..7
    const int grp  = wid >> 1;        // 0..3: tiles t = grp mod 4
    const int wg   = wid & 1;         // warp-in-group: rows wg*32..wg*32+31
    const int lt   = tid & 63;        // thread id within group
    const int m0   = blockIdx.x * BM;

    // ---- stage Q tile (swizzled), all 256 threads ----
    {
        const char* qg = (const char*)g_q + m0 * 128;   // 64 rows x 128B
        int row = tid >> 2;
        int ch  = (tid & 3) * 32;
        uint32_t sw0 = (uint32_t)row * 128 + (uint32_t)((ch)      ^ ((row & 7) << 4));
        uint32_t sw1 = (uint32_t)row * 128 + (uint32_t)((ch + 16) ^ ((row & 7) << 4));
        *(uint4*)(sm + SM_Q + sw0) = *(const uint4*)(qg + row * 128 + ch);
        *(uint4*)(sm + SM_Q + sw1) = *(const uint4*)(qg + row * 128 + ch + 16);
    }

    const uint32_t ring = sb + SM_KV + (uint32_t)grp * 2 * KVBUF;
    prefetch_tile(ring,         grp,     lt);
    CP_COMMIT();
    prefetch_tile(ring + KVBUF, grp + 4, lt);
    CP_COMMIT();
    __syncthreads();

    // ---- Q A-fragments: 2 m-fragments (32 rows) per warp ----
    uint32_t qf[2][4][4];
    {
        uint32_t cxor = (uint32_t)(lane & 7) << 4;
        #pragma unroll
        for (int m = 0; m < 2; m++) {
            int qrow = wg * 32 + m * 16 + (lane & 15);
            uint32_t qbase = sb + SM_Q + (uint32_t)qrow * 128;
            #pragma unroll
            for (int ks = 0; ks < 4; ks++) {
                uint32_t ch = (uint32_t)(ks * 32 + ((lane >> 4) << 4));
                LDSM4(qf[m][ks], qbase + (ch ^ cxor));
            }
        }
    }

    float o0[8][4], o1[8][4];
    #pragma unroll
    for (int nt = 0; nt < 8; nt++)
        #pragma unroll
        for (int j = 0; j < 4; j++) { o0[nt][j] = 0.f; o1[nt][j] = 0.f; }
    float os0[4] = {0.f, 0.f, 0.f, 0.f};
    float os1[4] = {0.f, 0.f, 0.f, 0.f};
    const uint32_t onesb[2] = {0x3C003C00u, 0x3C003C00u};   // fp16 1.0 x4

    const uint32_t browB = (uint32_t)(lane & 7) * 128;
    const uint32_t cA = (uint32_t)((((lane >> 3) & 3) << 4) ^ ((lane & 7) << 4));
    const uint32_t cB = cA ^ 64u;
    const int barid = grp + 1;

    int slot = 0;
    for (int t = grp; t < NTILES; t += 4, slot ^= 1) {
        const uint32_t kv = ring + (uint32_t)slot * KVBUF;

        CP_WAIT1();
        BAR_GRP(barid);

        uint32_t sh0[8][2], sh1[8][2];
        #pragma unroll
        for (int nt = 0; nt < 8; nt++) {
            sh0[nt][0] = 0u; sh0[nt][1] = 0u;
            sh1[nt][0] = 0u; sh1[nt][1] = 0u;
        }

        uint32_t phi0[4][4], phi1[4][4];

        S_HALF(0);
        S_HALF(4);
        SOFTMAX_ONE(sh0, phi0, 0); SOFTMAX_ONE(sh1, phi1, 0);
        SOFTMAX_ONE(sh0, phi0, 1); SOFTMAX_ONE(sh1, phi1, 1);
        SOFTMAX_ONE(sh0, phi0, 2); SOFTMAX_ONE(sh1, phi1, 2);
        SOFTMAX_ONE(sh0, phi0, 3); SOFTMAX_ONE(sh1, phi1, 3);
        mma16816(os0, phi0[0], onesb); mma16816(os1, phi1[0], onesb);
        mma16816(os0, phi0[1], onesb); mma16816(os1, phi1[1], onesb);
        PV_QTR(0, cA, 0, 1);
        SOFTMAX_ONE(sh0, phi0, 4); SOFTMAX_ONE(sh1, phi1, 4);
        SOFTMAX_ONE(sh0, phi0, 5); SOFTMAX_ONE(sh1, phi1, 5);
        SOFTMAX_ONE(sh0, phi0, 6); SOFTMAX_ONE(sh1, phi1, 6);
        SOFTMAX_ONE(sh0, phi0, 7); SOFTMAX_ONE(sh1, phi1, 7);
        mma16816(os0, phi0[2], onesb); mma16816(os1, phi1[2], onesb);
        mma16816(os0, phi0[3], onesb); mma16816(os1, phi1[3], onesb);
        PV_QTR(4, cA, 0, 1);
        PV_QTR(0, cB, 2, 3);
        PV_QTR(4, cB, 2, 3);

        BAR_GRP(barid);
        if (t + 8 < NTILES)
            prefetch_tile(kv, t + 8, lt);
        CP_COMMIT();
    }

    float rs[4] = {os0[0], os0[2], os1[0], os1[2]};

    __syncthreads();
    float* sc = (float*)(sm + SM_KV);
    if (grp > 0) {
        float* d = sc + ((grp - 1) * 64 + lt) * 68;
        #pragma unroll
        for (int nt = 0; nt < 8; nt++) {
            #pragma unroll
            for (int j = 0; j < 4; j++) {
                d[nt * 4 + j]      = o0[nt][j];
                d[32 + nt * 4 + j] = o1[nt][j];
            }
        }
        d[64] = rs[0]; d[65] = rs[1]; d[66] = rs[2]; d[67] = rs[3];
    }
    __syncthreads();
    if (grp == 0) {
        #pragma unroll
        for (int g = 0; g < 3; g++) {
            const float* d = sc + (g * 64 + lt) * 68;
            #pragma unroll
            for (int nt = 0; nt < 8; nt++) {
                #pragma unroll
                for (int j = 0; j < 4; j++) {
                    o0[nt][j] += d[nt * 4 + j];
                    o1[nt][j] += d[32 + nt * 4 + j];
                }
            }
            rs[0] += d[64]; rs[1] += d[65]; rs[2] += d[66]; rs[3] += d[67];
        }

        const float inv[4] = {1.f / rs[0], 1.f / rs[1], 1.f / rs[2], 1.f / rs[3]};

        const int r0 = lane >> 2;
        const int c0 = (lane & 3) * 2;
        #pragma unroll
        for (int m = 0; m < 2; m++) {
            const int mrow = m0 + wg * 32 + m * 16 + r0;
            const float ia = inv[m * 2], ib = inv[m * 2 + 1];
            #pragma unroll
            for (int nt = 0; nt < 8; nt++) {
                const float* oo = m ? o1[nt] : o0[nt];
                float2 v0 = make_float2(oo[0] * ia, oo[1] * ia);
                float2 v1 = make_float2(oo[2] * ib, oo[3] * ib);
                *(float2*)(out + (size_t)mrow * 64 + nt * 8 + c0)       = v0;
                *(float2*)(out + (size_t)(mrow + 8) * 64 + nt * 8 + c0) = v1;
            }
        }
    }
}

// ===========================================================================
extern "C" void kernel_launch(void* const* d_in, const int* in_sizes, int n_in,
                              void* d_out, int out_size)
{
    const float* hid = (const float*)d_in[0];
    const float* wq  = (const float*)d_in[1];
    const float* wk  = (const float*)d_in[2];
    const float* wv  = (const float*)d_in[3];
    float* out = (float*)d_out;

    cudaFuncSetAttribute(qkv_tc,
                         cudaFuncAttributeMaxDynamicSharedMemorySize, QT_SMEM);
    cudaFuncSetAttribute(attn_mma,
                         cudaFuncAttributeMaxDynamicSharedMemorySize, SMEM_TOTAL);

    qkv_tc<<<N_TOK / 64, 256, QT_SMEM>>>(hid, wq, wk, wv);
    attn_mma<<<N_TOK / BM, 256, SMEM_TOTAL>>>(out);
}

// round 17
// speedup vs baseline: 1.4773x; 1.4773x over previous
#include <cuda_runtime.h>
#include <cuda_fp16.h>
#include <cstdint>
#include <math.h>

#define N_TOK 8192
#define C_DIM 128
#define D_DIM 64

#define BM 64
#define BN 64
#define NTILES (N_TOK / BN)

// ===========================================================================
// Globals (allocation-free scratch), all fp16
// ===========================================================================
__device__ __half g_q [N_TOK * D_DIM];   // [n][d], pre-scaled by log2e/8
__device__ __half g_k [N_TOK * D_DIM];   // [n][d]
__device__ __half g_vT[D_DIM * N_TOK];   // [d][n]

// ===========================================================================
// PTX helpers (base-ISA only)
// ===========================================================================
__device__ __forceinline__ uint32_t smem_u32(const void* p) {
    uint32_t a;
    asm("{ .reg .u64 t; cvta.to.shared.u64 t, %1; cvt.u32.u64 %0, t; }"
        : "=r"(a) : "l"(p));
    return a;
}
#define CP16(dst, src) \
    asm volatile("cp.async.cg.shared.global [%0], [%1], 16;" \
        :: "r"(dst), "l"(src))
#define CP_COMMIT() asm volatile("cp.async.commit_group;")
#define CP_WAIT1()  asm volatile("cp.async.wait_group 1;" ::: "memory")
#define BAR_GRP(id) \
    asm volatile("bar.sync %0, 64;" :: "r"(id) : "memory")

#define LDSM4(r, addr) \
    asm volatile("ldmatrix.sync.aligned.m8n8.x4.shared.b16 {%0,%1,%2,%3}, [%4];" \
        : "=r"((r)[0]), "=r"((r)[1]), "=r"((r)[2]), "=r"((r)[3]) : "r"(addr))

__device__ __forceinline__ void mma16816(float d[4], const uint32_t a[4],
                                         const uint32_t b[2]) {
    asm volatile(
        "mma.sync.aligned.m16n8k16.row.col.f32.f16.f16.f32 "
        "{%0,%1,%2,%3}, {%4,%5,%6,%7}, {%8,%9}, {%0,%1,%2,%3};"
        : "+f"(d[0]), "+f"(d[1]), "+f"(d[2]), "+f"(d[3])
        : "r"(a[0]), "r"(a[1]), "r"(a[2]), "r"(a[3]), "r"(b[0]), "r"(b[1]));
}

// packs: result.lo = f16(a), result.hi = f16(b)
#define CVT_F16X2(result, a, b) \
    asm("cvt.rn.f16x2.f32 %0, %1, %2;" : "=r"(result) : "f"(b), "f"(a))
// packed fp16x2 exp2 (scores pre-scaled by log2e)
#define HEX2(r, x) asm("ex2.approx.f16x2 %0, %1;" : "=r"(r) : "r"(x))
// packed fp16x2 add (fma pipe)
#define HADD2(d, a, b) \
    asm("add.rn.f16x2 %0, %1, %2;" : "=r"(d) : "r"(a), "r"(b))

// ===========================================================================
// Kernel 1: tensor-core QKV (W converted in-kernel), unchanged from R15.
// ===========================================================================
#define QT_XLO 0
#define QT_XHI 8192
#define QT_W   16384
#define QT_VS  65536
#define QT_SMEM (QT_VS + 64 * 72 * 2)     // 74752 bytes

__global__ __launch_bounds__(256) void qkv_tc(
    const float* __restrict__ hid,
    const float* __restrict__ wq,
    const float* __restrict__ wk,
    const float* __restrict__ wv)
{
    extern __shared__ char sm[];
    const uint32_t sb = smem_u32(sm);
    const int tid  = threadIdx.x;
    const int lane = tid & 31;
    const int w    = tid >> 5;
    const int n0   = blockIdx.x * 64;
    const int bt   = n0 >> 8;
    const int hw0  = n0 & 255;
    const float* base = hid + (size_t)bt * (C_DIM * 256) + hw0;

    #pragma unroll
    for (int m = 0; m < 3; m++) {
        const float* wm = (m == 0) ? wq : (m == 1) ? wk : wv;
        const float sc = (m == 0) ? 0.1803368801f : 1.0f;   // /8 * log2e
        #pragma unroll
        for (int i = 0; i < 16; i++) {
            int id = tid + i * 256;
            int o  = id & 63;
            int c2 = id >> 6;
            float f0 = __ldg(wm + (2 * c2)     * 64 + o) * sc;
            float f1 = __ldg(wm + (2 * c2 + 1) * 64 + o) * sc;
            uint32_t h;
            CVT_F16X2(h, f0, f1);
            uint32_t tile = QT_W + (uint32_t)(m * 2 + (c2 >> 5)) * 8192;
            uint32_t off = (uint32_t)o * 128
                         + (uint32_t)(((c2 & 31) * 4) ^ ((o & 7) << 4));
            *(uint32_t*)(sm + tile + off) = h;
        }
    }

    #pragma unroll
    for (int i = 0; i < 16; i++) {
        int idx = tid + i * 256;
        int r = idx & 63, c2 = idx >> 6;
        float f0 = base[(2 * c2)     * 256 + r];
        float f1 = base[(2 * c2 + 1) * 256 + r];
        __half2 h = __floats2half2_rn(f0, f1);
        uint32_t tile = (c2 < 32) ? QT_XLO : QT_XHI;
        uint32_t boff = (uint32_t)r * 128
                      + (uint32_t)(((c2 & 31) * 4) ^ ((r & 7) << 4));
        *(__half2*)(sm + tile + boff) = h;
    }
    __syncthreads();

    const int r0 = (w & 3) * 16;
    uint32_t af[8][4];
    {
        uint32_t cxor = (uint32_t)(lane & 7) << 4;
        uint32_t rowb = sb + (uint32_t)(r0 + (lane & 15)) * 128;
        #pragma unroll
        for (int ks = 0; ks < 8; ks++) {
            uint32_t tile = (ks < 4) ? QT_XLO : QT_XHI;
            uint32_t ch = (uint32_t)((ks & 3) * 32 + ((lane >> 4) << 4));
            LDSM4(af[ks], rowb + tile + (ch ^ cxor));
        }
    }

    const uint32_t browB = (uint32_t)(lane & 7) * 128;
    const uint32_t cA = (uint32_t)((((lane >> 3) & 3) << 4) ^ ((lane & 7) << 4));
    const uint32_t cB = cA ^ 64u;

    float oq[8][4];
    #pragma unroll
    for (int nb = 0; nb < 8; nb++)
        #pragma unroll
        for (int j = 0; j < 4; j++) oq[nb][j] = 0.f;
    {
        uint32_t wbase = sb + QT_W + ((w < 4) ? 0 : 16384);
        #pragma unroll
        for (int nb = 0; nb < 8; nb++) {
            uint32_t rl = wbase + (uint32_t)nb * 1024 + browB;
            uint32_t rh = rl + 8192;
            uint32_t b01[4], b23[4], b45[4], b67[4];
            LDSM4(b01, rl + cA); LDSM4(b23, rl + cB);
            LDSM4(b45, rh + cA); LDSM4(b67, rh + cB);
            mma16816(oq[nb], af[0], b01 + 0); mma16816(oq[nb], af[1], b01 + 2);
            mma16816(oq[nb], af[2], b23 + 0); mma16816(oq[nb], af[3], b23 + 2);
            mma16816(oq[nb], af[4], b45 + 0); mma16816(oq[nb], af[5], b45 + 2);
            mma16816(oq[nb], af[6], b67 + 0); mma16816(oq[nb], af[7], b67 + 2);
        }
    }
    float ov[4][4];
    #pragma unroll
    for (int j = 0; j < 4; j++)
        #pragma unroll
        for (int c = 0; c < 4; c++) ov[j][c] = 0.f;
    const int nb0 = (w < 4) ? 0 : 4;
    {
        uint32_t vbase = sb + QT_W + 32768;
        #pragma unroll
        for (int j = 0; j < 4; j++) {
            uint32_t rl = vbase + (uint32_t)(nb0 + j) * 1024 + browB;
            uint32_t rh = rl + 8192;
            uint32_t b01[4], b23[4], b45[4], b67[4];
            LDSM4(b01, rl + cA); LDSM4(b23, rl + cB);
            LDSM4(b45, rh + cA); LDSM4(b67, rh + cB);
            mma16816(ov[j], af[0], b01 + 0); mma16816(ov[j], af[1], b01 + 2);
            mma16816(ov[j], af[2], b23 + 0); mma16816(ov[j], af[3], b23 + 2);
            mma16816(ov[j], af[4], b45 + 0); mma16816(ov[j], af[5], b45 + 2);
            mma16816(ov[j], af[6], b67 + 0); mma16816(ov[j], af[7], b67 + 2);
        }
    }

    {
        __half* dst = (w < 4) ? g_q : g_k;
        const int row = r0 + (lane >> 2);
        const int c0  = (lane & 3) * 2;
        #pragma unroll
        for (int nb = 0; nb < 8; nb++) {
            *(__half2*)(dst + (size_t)(n0 + row) * 64 + nb * 8 + c0)
                = __floats2half2_rn(oq[nb][0], oq[nb][1]);
            *(__half2*)(dst + (size_t)(n0 + row + 8) * 64 + nb * 8 + c0)
                = __floats2half2_rn(oq[nb][2], oq[nb][3]);
        }
    }
    {
        __half* vsh = (__half*)(sm + QT_VS);
        const int row = r0 + (lane >> 2);
        const int c0  = (lane & 3) * 2;
        #pragma unroll
        for (int j = 0; j < 4; j++) {
            int col = (nb0 + j) * 8 + c0;
            vsh[(col    ) * 72 + row    ] = __float2half(ov[j][0]);
            vsh[(col + 1) * 72 + row    ] = __float2half(ov[j][1]);
            vsh[(col    ) * 72 + row + 8] = __float2half(ov[j][2]);
            vsh[(col + 1) * 72 + row + 8] = __float2half(ov[j][3]);
        }
    }
    __syncthreads();
    {
        __half* vsh = (__half*)(sm + QT_VS);
        #pragma unroll
        for (int i = 0; i < 2; i++) {
            int id = tid + i * 256;
            int d = id >> 3, ch = id & 7;
            uint4 u = *(uint4*)&vsh[d * 72 + ch * 8];
            *(uint4*)((char*)g_vT + (size_t)d * 16384 + n0 * 2 + ch * 16) = u;
        }
    }
}

// ===========================================================================
// Kernel 2: flash attention (R15 structure: fp32-accum S, CVT+HEX2 softmax)
// with row-sums moved to the fma pipe (HADD2 trees over phi fragments).
// 128 CTAs x 256 threads; FOUR decoupled 64-thread groups (2 warps each).
// ===========================================================================
#define SM_Q   0
#define SM_KV  8192
#define KVBUF  16384            // k 0 | v 8192
#define SMEM_TOTAL (SM_KV + 8 * KVBUF)    // 139264 bytes

__device__ __forceinline__ void prefetch_tile(uint32_t kvbuf, int t, int lt)
{
    #pragma unroll
    for (int i = 0; i < 8; i++) {
        int id = lt + i * 64;
        int row = id >> 3;
        int ch  = (id & 7) * 16;
        uint32_t sw = (uint32_t)row * 128 + (uint32_t)(ch ^ ((row & 7) << 4));
        CP16(kvbuf +         sw, (const char*)g_k  + t * 8192 + row * 128 + ch);
        CP16(kvbuf + 8192 + sw, (const char*)g_vT + (size_t)row * 16384 + t * 128 + ch);
    }
}

#define SOFTMAX_ONE(S, PHI, nt) do {                                          \
    uint32_t p01, p23;                                                        \
    CVT_F16X2(p01, S[nt][0], S[nt][1]);                                       \
    CVT_F16X2(p23, S[nt][2], S[nt][3]);                                       \
    const int kk = (nt) >> 1, u = ((nt) & 1) * 2;                             \
    HEX2(PHI[kk][u],     p01);                                                \
    HEX2(PHI[kk][u + 1], p23);                                                \
} while (0)

// row sums for one key-half (kk = K0,K1) on the fma pipe; rows r / r+8
#define ROWSUM(PHI, RSA, RSB, K0, K1) do {                                    \
    uint32_t ra, rb, ta, tb;                                                  \
    HADD2(ra, PHI[K0][0], PHI[K1][0]);                                        \
    HADD2(ta, PHI[K0][2], PHI[K1][2]);                                        \
    HADD2(ra, ra, ta);                                                        \
    HADD2(rb, PHI[K0][1], PHI[K1][1]);                                        \
    HADD2(tb, PHI[K0][3], PHI[K1][3]);                                        \
    HADD2(rb, rb, tb);                                                        \
    float2 fa = __half22float2(*(__half2*)&ra);                               \
    float2 fb = __half22float2(*(__half2*)&rb);                               \
    RSA += fa.x + fa.y;                                                       \
    RSB += fb.x + fb.y;                                                       \
} while (0)

#define S_HALF(base) do {                                                     \
    uint32_t B[4][8];                                                         \
    _Pragma("unroll")                                                         \
    for (int j = 0; j < 4; j++) {                                             \
        uint32_t rb = kv + (uint32_t)((base) + j) * 1024 + browB;             \
        LDSM4(&B[j][0], rb + cA);                                             \
        LDSM4(&B[j][4], rb + cB);                                             \
    }                                                                         \
    _Pragma("unroll")                                                         \
    for (int ks = 0; ks < 4; ks++)                                            \
        _Pragma("unroll")                                                     \
        for (int j = 0; j < 4; j++) {                                         \
            mma16816(s0[(base) + j], qf[0][ks], &B[j][ks * 2]);               \
            mma16816(s1[(base) + j], qf[1][ks], &B[j][ks * 2]);               \
        }                                                                     \
} while (0)

#define PV_QTR(base, COFF, PA, PB) do {                                       \
    uint32_t B[4][4];                                                         \
    _Pragma("unroll")                                                         \
    for (int j = 0; j < 4; j++) {                                             \
        uint32_t rb = kv + 8192 + (uint32_t)((base) + j) * 1024 + browB;      \
        LDSM4(&B[j][0], rb + (COFF));                                         \
    }                                                                         \
    _Pragma("unroll")                                                         \
    for (int j = 0; j < 4; j++) {                                             \
        mma16816(o0[(base) + j], phi0[PA], &B[j][0]);                         \
        mma16816(o1[(base) + j], phi1[PA], &B[j][0]);                         \
    }                                                                         \
    _Pragma("unroll")                                                         \
    for (int j = 0; j < 4; j++) {                                             \
        mma16816(o0[(base) + j], phi0[PB], &B[j][2]);                         \
        mma16816(o1[(base) + j], phi1[PB], &B[j][2]);                         \
    }                                                                         \
} while (0)

__global__ __launch_bounds__(256, 1) void attn_mma(float* __restrict__ out)
{
    extern __shared__ char sm[];
    const uint32_t sb = smem_u32(sm);
    const int tid  = threadIdx.x;
    const int lane = tid & 31;
    const int wid  = tid >> 5;        // 0..7
    const int grp  = wid >> 1;        // 0..3: tiles t = grp mod 4
    const int wg   = wid & 1;         // warp-in-group: rows wg*32..wg*32+31
    const int lt   = tid & 63;        // thread id within group
    const int m0   = blockIdx.x * BM;

    // ---- stage Q tile (swizzled), all 256 threads ----
    {
        const char* qg = (const char*)g_q + m0 * 128;   // 64 rows x 128B
        int row = tid >> 2;
        int ch  = (tid & 3) * 32;
        uint32_t sw0 = (uint32_t)row * 128 + (uint32_t)((ch)      ^ ((row & 7) << 4));
        uint32_t sw1 = (uint32_t)row * 128 + (uint32_t)((ch + 16) ^ ((row & 7) << 4));
        *(uint4*)(sm + SM_Q + sw0) = *(const uint4*)(qg + row * 128 + ch);
        *(uint4*)(sm + SM_Q + sw1) = *(const uint4*)(qg + row * 128 + ch + 16);
    }

    const uint32_t ring = sb + SM_KV + (uint32_t)grp * 2 * KVBUF;
    prefetch_tile(ring,         grp,     lt);
    CP_COMMIT();
    prefetch_tile(ring + KVBUF, grp + 4, lt);
    CP_COMMIT();
    __syncthreads();

    // ---- Q A-fragments: 2 m-fragments (32 rows) per warp ----
    uint32_t qf[2][4][4];
    {
        uint32_t cxor = (uint32_t)(lane & 7) << 4;
        #pragma unroll
        for (int m = 0; m < 2; m++) {
            int qrow = wg * 32 + m * 16 + (lane & 15);
            uint32_t qbase = sb + SM_Q + (uint32_t)qrow * 128;
            #pragma unroll
            for (int ks = 0; ks < 4; ks++) {
                uint32_t ch = (uint32_t)(ks * 32 + ((lane >> 4) << 4));
                LDSM4(qf[m][ks], qbase + (ch ^ cxor));
            }
        }
    }

    float o0[8][4], o1[8][4];
    #pragma unroll
    for (int nt = 0; nt < 8; nt++)
        #pragma unroll
        for (int j = 0; j < 4; j++) { o0[nt][j] = 0.f; o1[nt][j] = 0.f; }
    float rs[4] = {0.f, 0.f, 0.f, 0.f};   // {m0.rowA, m0.rowB, m1.rowA, m1.rowB}

    const uint32_t browB = (uint32_t)(lane & 7) * 128;
    const uint32_t cA = (uint32_t)((((lane >> 3) & 3) << 4) ^ ((lane & 7) << 4));
    const uint32_t cB = cA ^ 64u;
    const int barid = grp + 1;

    int slot = 0;
    for (int t = grp; t < NTILES; t += 4, slot ^= 1) {
        const uint32_t kv = ring + (uint32_t)slot * KVBUF;

        CP_WAIT1();
        BAR_GRP(barid);

        float s0[8][4], s1[8][4];
        #pragma unroll
        for (int nt = 0; nt < 8; nt++)
            #pragma unroll
            for (int j = 0; j < 4; j++) { s0[nt][j] = 0.f; s1[nt][j] = 0.f; }

        uint32_t phi0[4][4], phi1[4][4];

        S_HALF(0);
        S_HALF(4);
        SOFTMAX_ONE(s0, phi0, 0); SOFTMAX_ONE(s1, phi1, 0);
        SOFTMAX_ONE(s0, phi0, 1); SOFTMAX_ONE(s1, phi1, 1);
        SOFTMAX_ONE(s0, phi0, 2); SOFTMAX_ONE(s1, phi1, 2);
        SOFTMAX_ONE(s0, phi0, 3); SOFTMAX_ONE(s1, phi1, 3);
        ROWSUM(phi0, rs[0], rs[1], 0, 1);
        ROWSUM(phi1, rs[2], rs[3], 0, 1);
        PV_QTR(0, cA, 0, 1);
        SOFTMAX_ONE(s0, phi0, 4); SOFTMAX_ONE(s1, phi1, 4);
        SOFTMAX_ONE(s0, phi0, 5); SOFTMAX_ONE(s1, phi1, 5);
        SOFTMAX_ONE(s0, phi0, 6); SOFTMAX_ONE(s1, phi1, 6);
        SOFTMAX_ONE(s0, phi0, 7); SOFTMAX_ONE(s1, phi1, 7);
        ROWSUM(phi0, rs[0], rs[1], 2, 3);
        ROWSUM(phi1, rs[2], rs[3], 2, 3);
        PV_QTR(4, cA, 0, 1);
        PV_QTR(0, cB, 2, 3);
        PV_QTR(4, cB, 2, 3);

        BAR_GRP(barid);
        if (t + 8 < NTILES)
            prefetch_tile(kv, t + 8, lt);
        CP_COMMIT();
    }

    // ---- combine the four groups (reuse KV smem as scratch) ----
    __syncthreads();
    float* sc = (float*)(sm + SM_KV);
    if (grp > 0) {
        float* d = sc + ((grp - 1) * 64 + lt) * 68;
        #pragma unroll
        for (int nt = 0; nt < 8; nt++) {
            #pragma unroll
            for (int j = 0; j < 4; j++) {
                d[nt * 4 + j]      = o0[nt][j];
                d[32 + nt * 4 + j] = o1[nt][j];
            }
        }
        d[64] = rs[0]; d[65] = rs[1]; d[66] = rs[2]; d[67] = rs[3];
    }
    __syncthreads();
    if (grp == 0) {
        #pragma unroll
        for (int g = 0; g < 3; g++) {
            const float* d = sc + (g * 64 + lt) * 68;
            #pragma unroll
            for (int nt = 0; nt < 8; nt++) {
                #pragma unroll
                for (int j = 0; j < 4; j++) {
                    o0[nt][j] += d[nt * 4 + j];
                    o1[nt][j] += d[32 + nt * 4 + j];
                }
            }
            rs[0] += d[64]; rs[1] += d[65]; rs[2] += d[66]; rs[3] += d[67];
        }

        // quad reduction: lanes sharing a row hold disjoint key-columns
        #pragma unroll
        for (int r = 0; r < 4; r++) {
            rs[r] += __shfl_xor_sync(0xffffffffu, rs[r], 1);
            rs[r] += __shfl_xor_sync(0xffffffffu, rs[r], 2);
        }
        const float inv[4] = {1.f / rs[0], 1.f / rs[1], 1.f / rs[2], 1.f / rs[3]};

        const int r0 = lane >> 2;
        const int c0 = (lane & 3) * 2;
        #pragma unroll
        for (int m = 0; m < 2; m++) {
            const int mrow = m0 + wg * 32 + m * 16 + r0;
            const float ia = inv[m * 2], ib = inv[m * 2 + 1];
            #pragma unroll
            for (int nt = 0; nt < 8; nt++) {
                const float* oo = m ? o1[nt] : o0[nt];
                float2 v0 = make_float2(oo[0] * ia, oo[1] * ia);
                float2 v1 = make_float2(oo[2] * ib, oo[3] * ib);
                *(float2*)(out + (size_t)mrow * 64 + nt * 8 + c0)       = v0;
                *(float2*)(out + (size_t)(mrow + 8) * 64 + nt * 8 + c0) = v1;
            }
        }
    }
}

// ===========================================================================
extern "C" void kernel_launch(void* const* d_in, const int* in_sizes, int n_in,
                              void* d_out, int out_size)
{
    const float* hid = (const float*)d_in[0];
    const float* wq  = (const float*)d_in[1];
    const float* wk  = (const float*)d_in[2];
    const float* wv  = (const float*)d_in[3];
    float* out = (float*)d_out;

    cudaFuncSetAttribute(qkv_tc,
                         cudaFuncAttributeMaxDynamicSharedMemorySize, QT_SMEM);
    cudaFuncSetAttribute(attn_mma,
                         cudaFuncAttributeMaxDynamicSharedMemorySize, SMEM_TOTAL);

    qkv_tc<<<N_TOK / 64, 256, QT_SMEM>>>(hid, wq, wk, wv);
    attn_mma<<<N_TOK / BM, 256, SMEM_TOTAL>>>(out);
}